// round 7
// baseline (speedup 1.0000x reference)
#include <cuda_runtime.h>
#include <cstdint>

#define NN 50000
#define EE 800000
#define GG 1024
#define DD 128
#define HH 4
#define LL 3
#define NODE_DIM 78
#define HID 1024

// ---------------- scratch (device globals; no allocation allowed) ----------
__device__ float g_h[NN * DD];                 // 25.6 MB
__device__ float g_hp[(size_t)NN * HH * DD];   // 102.4 MB
__device__ float g_hn[NN * DD];                // 25.6 MB
__device__ float g_as[NN * HH];
__device__ float g_ad[NN * HH];
__device__ int   g_rowptr[NN + 1];
__device__ int   g_cnt[NN];
__device__ int   g_col[EE];
__device__ float g_pooled[GG * DD];
__device__ int   g_gcnt[GG];
__device__ float g_hidden[GG * HID];
// transposed / K-padded weights: W1T[128][128], W2T[128][128], lin_wT[3][512][128]
__device__ float g_wT[2 * 128 * 128 + 3 * 512 * 128];

__device__ __forceinline__ uint32_t cvt_tf32(float f) {
    uint32_t u;
    asm("cvt.rna.tf32.f32 %0, %1;" : "=r"(u) : "f"(f));
    return u;
}

// ---------------- utility kernels ------------------------------------------
__global__ void zero_int_kernel(int* p, int n) {
    int i = blockIdx.x * blockDim.x + threadIdx.x;
    if (i < n) p[i] = 0;
}
__global__ void zero_float_kernel(float* p, int n) {
    int i = blockIdx.x * blockDim.x + threadIdx.x;
    if (i < n) p[i] = 0.f;
}

// transpose + pad-K: src [K, Nsrc] row-major -> dst [Nsrc][128], zeros for k>=K
__global__ void transpose_pad_kernel(const float* __restrict__ src, int K, int Nsrc,
                                     float* __restrict__ dst) {
    __shared__ float t[32][33];
    int n0 = blockIdx.x * 32, k0 = blockIdx.y * 32;
    int tx = threadIdx.x, ty = threadIdx.y;
#pragma unroll
    for (int i = 0; i < 32; i += 8) {
        int k = k0 + ty + i, n = n0 + tx;
        t[ty + i][tx] = (k < K && n < Nsrc) ? src[(size_t)k * Nsrc + n] : 0.f;
    }
    __syncthreads();
#pragma unroll
    for (int i = 0; i < 32; i += 8) {
        int n = n0 + ty + i, k = k0 + tx;
        if (n < Nsrc) dst[(size_t)n * 128 + k] = t[tx][ty + i];
    }
}

// ---------------- tf32 mma.sync GEMM, tile 128x128, K<=128, fused epilogue -
// SMEM floats: As[128][132], Bs[128][132], asbuf[128], adbuf[128]
#define LDS_STRIDE 132
#define AS_OFF 0
#define BS_OFF (128 * LDS_STRIDE)
#define AT_OFF (2 * 128 * LDS_STRIDE)
#define SM_FLOATS (2 * 128 * LDS_STRIDE + 256)
#define SM_BYTES (SM_FLOATS * 4)

__global__ void __launch_bounds__(256)
tf32_gemm_fused(const float* __restrict__ A, int M, int Ksrc,
                const float* __restrict__ Bt,     // [nChunks*128][128] pre-transposed
                const float* __restrict__ bias,   // global-col indexed or null
                float* __restrict__ C, int c_stride,
                int relu,
                const float* __restrict__ attS,   // global-col indexed or null
                const float* __restrict__ attD,
                float* __restrict__ asOut, float* __restrict__ adOut)
{
    extern __shared__ float sm[];
    float* As = sm + AS_OFF;
    float* Bs = sm + BS_OFF;
    float* asbuf = sm + AT_OFF;
    float* adbuf = sm + AT_OFF + 128;

    const int tid = threadIdx.x;
    const int wid = tid >> 5, lane = tid & 31;
    const int grp = lane >> 2, tig = lane & 3;
    const int wm = wid & 3, wn = wid >> 2;      // 4 x 2 warp grid
    const int nc = blockIdx.x;
    const int m0 = blockIdx.y * 128;
    const int rows = min(128, M - m0);
    const int colg0 = nc * 128;

    // ---- load tiles to SMEM (convert to tf32 bits) ----
    if (Ksrc == 128) {
        const float4* src = (const float4*)(A + (size_t)m0 * 128);
        for (int idx = tid; idx < 128 * 32; idx += 256) {
            int row = idx >> 5, q = idx & 31;
            float4 v = make_float4(0.f, 0.f, 0.f, 0.f);
            if (row < rows) v = src[row * 32 + q];
            float4 o;
            o.x = __uint_as_float(cvt_tf32(v.x));
            o.y = __uint_as_float(cvt_tf32(v.y));
            o.z = __uint_as_float(cvt_tf32(v.z));
            o.w = __uint_as_float(cvt_tf32(v.w));
            *(float4*)(As + row * LDS_STRIDE + q * 4) = o;
        }
    } else {
        for (int idx = tid; idx < 128 * 128; idx += 256) {
            int row = idx >> 7, c = idx & 127;
            float v = (row < rows && c < Ksrc) ? A[(size_t)(m0 + row) * Ksrc + c] : 0.f;
            As[row * LDS_STRIDE + c] = __uint_as_float(cvt_tf32(v));
        }
    }
    {
        const float4* src = (const float4*)(Bt + (size_t)nc * 128 * 128);
        for (int idx = tid; idx < 128 * 32; idx += 256) {
            int row = idx >> 5, q = idx & 31;
            float4 v = src[row * 32 + q];
            float4 o;
            o.x = __uint_as_float(cvt_tf32(v.x));
            o.y = __uint_as_float(cvt_tf32(v.y));
            o.z = __uint_as_float(cvt_tf32(v.z));
            o.w = __uint_as_float(cvt_tf32(v.w));
            *(float4*)(Bs + row * LDS_STRIDE + q * 4) = o;
        }
    }
    if (tid < 128) { asbuf[tid] = 0.f; adbuf[tid] = 0.f; }
    __syncthreads();

    // ---- main MMA loop ----
    float acc[2][8][4];
#pragma unroll
    for (int mi = 0; mi < 2; mi++)
#pragma unroll
        for (int ni = 0; ni < 8; ni++)
#pragma unroll
            for (int q = 0; q < 4; q++) acc[mi][ni][q] = 0.f;

#pragma unroll
    for (int ks = 0; ks < 16; ks++) {
        const int k0 = ks * 8;
        uint32_t a[2][4];
#pragma unroll
        for (int mi = 0; mi < 2; mi++) {
            int rb = wm * 32 + mi * 16 + grp;
            a[mi][0] = __float_as_uint(As[rb * LDS_STRIDE + k0 + tig]);
            a[mi][1] = __float_as_uint(As[(rb + 8) * LDS_STRIDE + k0 + tig]);
            a[mi][2] = __float_as_uint(As[rb * LDS_STRIDE + k0 + tig + 4]);
            a[mi][3] = __float_as_uint(As[(rb + 8) * LDS_STRIDE + k0 + tig + 4]);
        }
        uint32_t b[8][2];
#pragma unroll
        for (int ni = 0; ni < 8; ni++) {
            int cb = wn * 64 + ni * 8 + grp;
            b[ni][0] = __float_as_uint(Bs[cb * LDS_STRIDE + k0 + tig]);
            b[ni][1] = __float_as_uint(Bs[cb * LDS_STRIDE + k0 + tig + 4]);
        }
#pragma unroll
        for (int mi = 0; mi < 2; mi++)
#pragma unroll
            for (int ni = 0; ni < 8; ni++) {
                asm volatile(
                    "mma.sync.aligned.m16n8k8.row.col.f32.tf32.tf32.f32 "
                    "{%0,%1,%2,%3}, {%4,%5,%6,%7}, {%8,%9}, {%0,%1,%2,%3};"
                    : "+f"(acc[mi][ni][0]), "+f"(acc[mi][ni][1]),
                      "+f"(acc[mi][ni][2]), "+f"(acc[mi][ni][3])
                    : "r"(a[mi][0]), "r"(a[mi][1]), "r"(a[mi][2]), "r"(a[mi][3]),
                      "r"(b[ni][0]), "r"(b[ni][1]));
            }
    }

    // ---- epilogue: bias/relu/store + fused attention dots ----
#pragma unroll
    for (int mi = 0; mi < 2; mi++) {
        const int r0 = wm * 32 + mi * 16 + grp;
        const int r1 = r0 + 8;
        const int gm0 = m0 + r0, gm1 = m0 + r1;
        float aS0 = 0.f, aD0 = 0.f, aS1 = 0.f, aD1 = 0.f;
#pragma unroll
        for (int ni = 0; ni < 8; ni++) {
            const int col = wn * 64 + ni * 8 + tig * 2;
            const int cg = colg0 + col;
            float v0 = acc[mi][ni][0], v1 = acc[mi][ni][1];
            float v2 = acc[mi][ni][2], v3 = acc[mi][ni][3];
            if (bias) {
                float b0 = bias[cg], b1 = bias[cg + 1];
                v0 += b0; v1 += b1; v2 += b0; v3 += b1;
            }
            if (relu) {
                v0 = fmaxf(v0, 0.f); v1 = fmaxf(v1, 0.f);
                v2 = fmaxf(v2, 0.f); v3 = fmaxf(v3, 0.f);
            }
            if (attS) {
                float s0 = attS[cg], s1 = attS[cg + 1];
                float d0 = attD[cg], d1 = attD[cg + 1];
                aS0 += v0 * s0 + v1 * s1;
                aD0 += v0 * d0 + v1 * d1;
                aS1 += v2 * s0 + v3 * s1;
                aD1 += v2 * d0 + v3 * d1;
            }
            if (gm0 < M) *(float2*)(C + (size_t)gm0 * c_stride + cg) = make_float2(v0, v1);
            if (gm1 < M) *(float2*)(C + (size_t)gm1 * c_stride + cg) = make_float2(v2, v3);
        }
        if (attS) {
            atomicAdd(&asbuf[r0], aS0);
            atomicAdd(&adbuf[r0], aD0);
            atomicAdd(&asbuf[r1], aS1);
            atomicAdd(&adbuf[r1], aD1);
        }
    }
    if (attS) {
        __syncthreads();
        if (tid < 128 && m0 + tid < M) {
            asOut[(m0 + tid) * HH + nc] = asbuf[tid];
            adOut[(m0 + tid) * HH + nc] = adbuf[tid];
        }
    }
}

// ---------------- SIMT SGEMM (small FC head only) ---------------------------
template <int BM, int BN, int BK, int TM, int TN>
__global__ void __launch_bounds__((BM / TM) * (BN / TN))
sgemm_kernel(const float* __restrict__ A, const float* __restrict__ B,
             const float* __restrict__ bias, float* __restrict__ C,
             int M, int N, int K, int relu)
{
    constexpr int TX = BN / TN;
    constexpr int TY = BM / TM;
    constexpr int THREADS = TX * TY;
    __shared__ float As[BK][BM];
    __shared__ float Bs[BK][BN];

    const int tid = threadIdx.x;
    const int tx = tid % TX;
    const int ty = tid / TX;
    const int row0 = blockIdx.y * BM;
    const int col0 = blockIdx.x * BN;

    float acc[TM][TN];
#pragma unroll
    for (int i = 0; i < TM; i++)
#pragma unroll
        for (int j = 0; j < TN; j++) acc[i][j] = 0.f;

    for (int k0 = 0; k0 < K; k0 += BK) {
        for (int i = tid; i < BM * BK; i += THREADS) {
            int m = i / BK, k = i % BK;
            int gm = row0 + m, gk = k0 + k;
            As[k][m] = (gm < M && gk < K) ? A[(size_t)gm * K + gk] : 0.f;
        }
        for (int i = tid; i < BK * BN; i += THREADS) {
            int k = i / BN, nn = i % BN;
            int gn = col0 + nn, gk = k0 + k;
            Bs[k][nn] = (gn < N && gk < K) ? B[(size_t)gk * N + gn] : 0.f;
        }
        __syncthreads();
#pragma unroll
        for (int k = 0; k < BK; k++) {
            float ra[TM], rb[TN];
#pragma unroll
            for (int i = 0; i < TM; i++) ra[i] = As[k][ty * TM + i];
#pragma unroll
            for (int j = 0; j < TN; j++) rb[j] = Bs[k][tx * TN + j];
#pragma unroll
            for (int i = 0; i < TM; i++)
#pragma unroll
                for (int j = 0; j < TN; j++) acc[i][j] += ra[i] * rb[j];
        }
        __syncthreads();
    }

#pragma unroll
    for (int i = 0; i < TM; i++) {
        int gm = row0 + ty * TM + i;
        if (gm >= M) continue;
#pragma unroll
        for (int j = 0; j < TN; j++) {
            int gn = col0 + tx * TN + j;
            if (gn >= N) continue;
            float v = acc[i][j];
            if (bias) v += bias[gn];
            if (relu) v = fmaxf(v, 0.f);
            C[(size_t)gm * N + gn] = v;
        }
    }
}

// ---------------- CSR build (edge_index is int32) ---------------------------
__global__ void hist_kernel(const int* __restrict__ ei, int* __restrict__ cnt) {
    int e = blockIdx.x * blockDim.x + threadIdx.x;
    if (e < EE) atomicAdd(&cnt[ei[EE + e]], 1);
}

__global__ void scan_kernel(const int* __restrict__ cnt, int* __restrict__ rowptr) {
    __shared__ int sh[1024];
    const int tid = threadIdx.x;
    int carry = 0;
    if (tid == 0) rowptr[0] = 0;
    for (int base = 0; base < NN; base += 1024) {
        int v = (base + tid < NN) ? cnt[base + tid] : 0;
        sh[tid] = v;
        __syncthreads();
        for (int off = 1; off < 1024; off <<= 1) {
            int t = (tid >= off) ? sh[tid - off] : 0;
            __syncthreads();
            sh[tid] += t;
            __syncthreads();
        }
        if (base + tid < NN) rowptr[base + tid + 1] = carry + sh[tid];
        int tot = sh[1023];
        __syncthreads();
        carry += tot;
    }
}

__global__ void scatter_kernel(const int* __restrict__ ei,
                               const int* __restrict__ rowptr,
                               int* __restrict__ cur, int* __restrict__ colA) {
    int e = blockIdx.x * blockDim.x + threadIdx.x;
    if (e < EE) {
        int d = ei[EE + e];
        int pos = atomicAdd(&cur[d], 1);
        colA[rowptr[d] + pos] = ei[e];
    }
}

// ---------------- GAT aggregation: segment softmax + weighted sum ----------
#define AGG_CHUNK 256
__global__ void gat_aggregate_kernel(const float* __restrict__ hp,
                                     const float* __restrict__ as_,
                                     const float* __restrict__ ad_,
                                     const int* __restrict__ rowptr,
                                     const int* __restrict__ col,
                                     const float* __restrict__ bias,
                                     float* __restrict__ hout) {
    const int n = blockIdx.x;
    const int tid = threadIdx.x;
    const int start = rowptr[n];
    const int deg = rowptr[n + 1] - start;
    const int total = deg + 1;

    float adh[HH];
#pragma unroll
    for (int h = 0; h < HH; h++) adh[h] = ad_[n * HH + h];

    __shared__ float4 red[128];
    __shared__ float  wbuf[AGG_CHUNK * HH];
    __shared__ int    sbuf[AGG_CHUNK];

    float lm[HH] = {-1e30f, -1e30f, -1e30f, -1e30f};
    for (int i = tid; i < total; i += 128) {
        int s = (i < deg) ? col[start + i] : n;
#pragma unroll
        for (int h = 0; h < HH; h++) {
            float e = as_[s * HH + h] + adh[h];
            e = e > 0.f ? e : 0.2f * e;
            lm[h] = fmaxf(lm[h], e);
        }
    }
    red[tid] = make_float4(lm[0], lm[1], lm[2], lm[3]);
    __syncthreads();
    for (int s = 64; s > 0; s >>= 1) {
        if (tid < s) {
            float4 a = red[tid], b = red[tid + s];
            red[tid] = make_float4(fmaxf(a.x, b.x), fmaxf(a.y, b.y),
                                   fmaxf(a.z, b.z), fmaxf(a.w, b.w));
        }
        __syncthreads();
    }
    float4 m4 = red[0];
    float mh[HH] = {m4.x, m4.y, m4.z, m4.w};
    __syncthreads();

    float num[HH] = {0.f, 0.f, 0.f, 0.f};
    float dl[HH] = {0.f, 0.f, 0.f, 0.f};
    for (int base = 0; base < total; base += AGG_CHUNK) {
        int cnt = min(AGG_CHUNK, total - base);
        for (int i = tid; i < cnt; i += 128) {
            int s = (base + i < deg) ? col[start + base + i] : n;
            sbuf[i] = s;
#pragma unroll
            for (int h = 0; h < HH; h++) {
                float e = as_[s * HH + h] + adh[h];
                e = e > 0.f ? e : 0.2f * e;
                float w = __expf(e - mh[h]);
                wbuf[i * HH + h] = w;
                dl[h] += w;
            }
        }
        __syncthreads();
#pragma unroll 4
        for (int i = 0; i < cnt; i++) {
            int s = sbuf[i];
            const float* hr = hp + (size_t)s * (HH * DD) + tid;
#pragma unroll
            for (int h = 0; h < HH; h++) num[h] += wbuf[i * HH + h] * hr[h * DD];
        }
        __syncthreads();
    }

    red[tid] = make_float4(dl[0], dl[1], dl[2], dl[3]);
    __syncthreads();
    for (int s = 64; s > 0; s >>= 1) {
        if (tid < s) {
            float4 a = red[tid], b = red[tid + s];
            red[tid] = make_float4(a.x + b.x, a.y + b.y, a.z + b.z, a.w + b.w);
        }
        __syncthreads();
    }
    float4 dn = red[0];
    float o = 0.25f * (num[0] / (dn.x + 1e-16f) + num[1] / (dn.y + 1e-16f) +
                       num[2] / (dn.z + 1e-16f) + num[3] / (dn.w + 1e-16f));
    hout[(size_t)n * DD + tid] = o + bias[tid];
}

// ---------------- pooling ---------------------------------------------------
__global__ void pool_accum_kernel(const float* __restrict__ hin,
                                  const int* __restrict__ batch,
                                  float* __restrict__ pooled, int* __restrict__ gcnt) {
    int n = blockIdx.x;
    int c = threadIdx.x;
    int g = batch[n];
    if (c == 0) atomicAdd(&gcnt[g], 1);
    atomicAdd(&pooled[g * DD + c], hin[(size_t)n * DD + c]);
}
__global__ void pool_finalize_kernel(float* __restrict__ pooled,
                                     const int* __restrict__ gcnt) {
    int g = blockIdx.x;
    int c = threadIdx.x;
    float cf = fmaxf((float)gcnt[g], 1.f);
    pooled[g * DD + c] /= cf;
}

// ---------------- launch ----------------------------------------------------
extern "C" void kernel_launch(void* const* d_in, const int* in_sizes, int n_in,
                              void* d_out, int out_size) {
    const float* x       = (const float*)d_in[0];
    const int*   ei      = (const int*)d_in[1];
    const int*   batch   = (const int*)d_in[2];
    const float* W1      = (const float*)d_in[3];
    const float* b1      = (const float*)d_in[4];
    const float* W2      = (const float*)d_in[5];
    const float* b2      = (const float*)d_in[6];
    const float* lin_w   = (const float*)d_in[7];
    const float* att_src = (const float*)d_in[8];
    const float* att_dst = (const float*)d_in[9];
    const float* conv_b  = (const float*)d_in[10];
    const float* gW1     = (const float*)d_in[11];
    const float* gb1     = (const float*)d_in[12];
    const float* gW2     = (const float*)d_in[13];
    const float* gb2     = (const float*)d_in[14];
    float*       out     = (float*)d_out;

    float *h, *hp, *hn, *as_, *ad_, *pooled, *hidden, *wT;
    int *rowptr, *cnt, *colA, *gcnt;
    cudaGetSymbolAddress((void**)&h, g_h);
    cudaGetSymbolAddress((void**)&hp, g_hp);
    cudaGetSymbolAddress((void**)&hn, g_hn);
    cudaGetSymbolAddress((void**)&as_, g_as);
    cudaGetSymbolAddress((void**)&ad_, g_ad);
    cudaGetSymbolAddress((void**)&rowptr, g_rowptr);
    cudaGetSymbolAddress((void**)&cnt, g_cnt);
    cudaGetSymbolAddress((void**)&colA, g_col);
    cudaGetSymbolAddress((void**)&pooled, g_pooled);
    cudaGetSymbolAddress((void**)&gcnt, g_gcnt);
    cudaGetSymbolAddress((void**)&hidden, g_hidden);
    cudaGetSymbolAddress((void**)&wT, g_wT);

    float* w1T = wT;                  // [128][128]
    float* w2T = wT + 128 * 128;      // [128][128]
    float* linT = wT + 2 * 128 * 128; // [3][512][128]

    cudaFuncSetAttribute(tf32_gemm_fused,
                         cudaFuncAttributeMaxDynamicSharedMemorySize, SM_BYTES);

    auto cdiv = [](int a, int b) { return (a + b - 1) / b; };
    const int MT = cdiv(NN, 128);  // 391 m-tiles

    // 0) transpose/pad weights
    transpose_pad_kernel<<<dim3(4, 4), dim3(32, 8)>>>(W1, NODE_DIM, DD, w1T);
    transpose_pad_kernel<<<dim3(4, 4), dim3(32, 8)>>>(W2, DD, DD, w2T);
    for (int l = 0; l < LL; l++)
        transpose_pad_kernel<<<dim3(16, 4), dim3(32, 8)>>>(
            lin_w + (size_t)l * DD * HH * DD, DD, HH * DD, linT + (size_t)l * 512 * 128);

    // 1) node MLP via tensor cores (tmp = hn)
    tf32_gemm_fused<<<dim3(1, MT), 256, SM_BYTES>>>(
        x, NN, NODE_DIM, w1T, b1, hn, DD, 1, nullptr, nullptr, nullptr, nullptr);
    tf32_gemm_fused<<<dim3(1, MT), 256, SM_BYTES>>>(
        hn, NN, DD, w2T, b2, h, DD, 0, nullptr, nullptr, nullptr, nullptr);

    // 2) CSR by destination
    zero_int_kernel<<<cdiv(NN, 256), 256>>>(cnt, NN);
    hist_kernel<<<cdiv(EE, 256), 256>>>(ei, cnt);
    scan_kernel<<<1, 1024>>>(cnt, rowptr);
    zero_int_kernel<<<cdiv(NN, 256), 256>>>(cnt, NN);
    scatter_kernel<<<cdiv(EE, 256), 256>>>(ei, rowptr, cnt, colA);

    // 3) GAT layers: fused projection + attention dots, then aggregate
    float* hin = h;
    float* hout = hn;
    for (int l = 0; l < LL; l++) {
        tf32_gemm_fused<<<dim3(HH, MT), 256, SM_BYTES>>>(
            hin, NN, DD, linT + (size_t)l * 512 * 128, nullptr, hp, HH * DD, 0,
            att_src + l * HH * DD, att_dst + l * HH * DD, as_, ad_);
        gat_aggregate_kernel<<<NN, 128>>>(hp, as_, ad_, rowptr, colA,
                                          conv_b + l * DD, hout);
        float* t = hin; hin = hout; hout = t;
    }

    // 4) global mean pool
    zero_float_kernel<<<cdiv(GG * DD, 256), 256>>>(pooled, GG * DD);
    zero_int_kernel<<<cdiv(GG, 256), 256>>>(gcnt, GG);
    pool_accum_kernel<<<NN, DD>>>(hin, batch, pooled, gcnt);
    pool_finalize_kernel<<<GG, DD>>>(pooled, gcnt);

    // 5) FC head
    sgemm_kernel<64, 64, 8, 4, 4><<<dim3(cdiv(HID, 64), cdiv(GG, 64)), 256>>>(
        pooled, gW1, gb1, hidden, GG, HID, DD, 1);
    sgemm_kernel<64, 64, 8, 4, 4><<<dim3(cdiv(DD, 64), cdiv(GG, 64)), 256>>>(
        hidden, gW2, gb2, out, GG, DD, HID, 0);
}

// round 8
// speedup vs baseline: 1.1747x; 1.1747x over previous
#include <cuda_runtime.h>
#include <cstdint>

#define NN 50000
#define EE 800000
#define GG 1024
#define DD 128
#define HH 4
#define LL 3
#define NODE_DIM 78
#define HID 1024

// ---------------- scratch (device globals; no allocation allowed) ----------
__device__ float g_h[NN * DD];                 // 25.6 MB
__device__ float g_hp[(size_t)NN * HH * DD];   // 102.4 MB
__device__ float g_hn[NN * DD];                // 25.6 MB
__device__ float g_as[NN * HH];
__device__ float g_ad[NN * HH];
__device__ int   g_rowptr[NN + 1];
__device__ int   g_cnt[NN];
__device__ int   g_col[EE];
__device__ float g_pooled[GG * DD];
__device__ int   g_gcnt[GG];
__device__ float g_hidden[GG * HID];
// transposed / K-padded weights: W1T, W2T, lin_wT[3][512][128], gW1T[1024][128]
__device__ float g_wT[2 * 128 * 128 + 3 * 512 * 128 + 1024 * 128];

__device__ __forceinline__ uint32_t cvt_tf32(float f) {
    uint32_t u;
    asm("cvt.rna.tf32.f32 %0, %1;" : "=r"(u) : "f"(f));
    return u;
}

// ---------------- utility kernels ------------------------------------------
__global__ void zero_int_kernel(int* p, int n) {
    int i = blockIdx.x * blockDim.x + threadIdx.x;
    if (i < n) p[i] = 0;
}
__global__ void zero_float_kernel(float* p, int n) {
    int i = blockIdx.x * blockDim.x + threadIdx.x;
    if (i < n) p[i] = 0.f;
}

// transpose + pad-K: src [K, Nsrc] row-major -> dst [Nsrc][128], zeros for k>=K
__global__ void transpose_pad_kernel(const float* __restrict__ src, int K, int Nsrc,
                                     float* __restrict__ dst) {
    __shared__ float t[32][33];
    int n0 = blockIdx.x * 32, k0 = blockIdx.y * 32;
    int tx = threadIdx.x, ty = threadIdx.y;
#pragma unroll
    for (int i = 0; i < 32; i += 8) {
        int k = k0 + ty + i, n = n0 + tx;
        t[ty + i][tx] = (k < K && n < Nsrc) ? src[(size_t)k * Nsrc + n] : 0.f;
    }
    __syncthreads();
#pragma unroll
    for (int i = 0; i < 32; i += 8) {
        int n = n0 + ty + i, k = k0 + tx;
        if (n < Nsrc) dst[(size_t)n * 128 + k] = t[tx][ty + i];
    }
}

// ---------------- tf32 mma.sync GEMM, tile 256x128, K<=128, fused epilogue -
// 512 threads = 16 warps in 8x2 grid. Each warp: 32 rows x 64 cols.
// SMEM floats: As[256][132], Bs[128][132], asbuf[256], adbuf[256]
#define LDS_STRIDE 132
#define BMROWS 256
#define GTHREADS 512
#define AS_OFF 0
#define BS_OFF (BMROWS * LDS_STRIDE)
#define AT_OFF (BS_OFF + 128 * LDS_STRIDE)
#define SM_FLOATS (AT_OFF + 2 * BMROWS)
#define SM_BYTES (SM_FLOATS * 4)

__global__ void __launch_bounds__(GTHREADS)
tf32_gemm_fused(const float* __restrict__ A, int M, int Ksrc,
                const float* __restrict__ Bt,     // [nChunks*128][128] pre-transposed
                const float* __restrict__ bias,   // global-col indexed or null
                float* __restrict__ C, int c_stride,
                int relu,
                const float* __restrict__ attS,   // global-col indexed or null
                const float* __restrict__ attD,
                float* __restrict__ asOut, float* __restrict__ adOut)
{
    extern __shared__ float sm[];
    float* As = sm + AS_OFF;
    float* Bs = sm + BS_OFF;
    float* asbuf = sm + AT_OFF;
    float* adbuf = sm + AT_OFF + BMROWS;

    const int tid = threadIdx.x;
    const int wid = tid >> 5, lane = tid & 31;
    const int grp = lane >> 2, tig = lane & 3;
    const int wm = wid & 7, wn = wid >> 3;      // 8 x 2 warp grid
    const int nc = blockIdx.x;
    const int m0 = blockIdx.y * BMROWS;
    const int rows = min(BMROWS, M - m0);
    const int colg0 = nc * 128;

    // ---- load tiles to SMEM (convert to tf32 bits) ----
    if (Ksrc == 128) {
        const float4* src = (const float4*)(A + (size_t)m0 * 128);
        for (int idx = tid; idx < BMROWS * 32; idx += GTHREADS) {
            int row = idx >> 5, q = idx & 31;
            float4 v = make_float4(0.f, 0.f, 0.f, 0.f);
            if (row < rows) v = src[row * 32 + q];
            float4 o;
            o.x = __uint_as_float(cvt_tf32(v.x));
            o.y = __uint_as_float(cvt_tf32(v.y));
            o.z = __uint_as_float(cvt_tf32(v.z));
            o.w = __uint_as_float(cvt_tf32(v.w));
            *(float4*)(As + row * LDS_STRIDE + q * 4) = o;
        }
    } else {
        for (int idx = tid; idx < BMROWS * 128; idx += GTHREADS) {
            int row = idx >> 7, c = idx & 127;
            float v = (row < rows && c < Ksrc) ? A[(size_t)(m0 + row) * Ksrc + c] : 0.f;
            As[row * LDS_STRIDE + c] = __uint_as_float(cvt_tf32(v));
        }
    }
    {
        const float4* src = (const float4*)(Bt + (size_t)nc * 128 * 128);
        for (int idx = tid; idx < 128 * 32; idx += GTHREADS) {
            int row = idx >> 5, q = idx & 31;
            float4 v = src[row * 32 + q];
            float4 o;
            o.x = __uint_as_float(cvt_tf32(v.x));
            o.y = __uint_as_float(cvt_tf32(v.y));
            o.z = __uint_as_float(cvt_tf32(v.z));
            o.w = __uint_as_float(cvt_tf32(v.w));
            *(float4*)(Bs + row * LDS_STRIDE + q * 4) = o;
        }
    }
    if (tid < BMROWS) { asbuf[tid] = 0.f; adbuf[tid] = 0.f; }
    __syncthreads();

    // ---- main MMA loop ----
    float acc[2][8][4];
#pragma unroll
    for (int mi = 0; mi < 2; mi++)
#pragma unroll
        for (int ni = 0; ni < 8; ni++)
#pragma unroll
            for (int q = 0; q < 4; q++) acc[mi][ni][q] = 0.f;

#pragma unroll
    for (int ks = 0; ks < 16; ks++) {
        const int k0 = ks * 8;
        uint32_t a[2][4];
#pragma unroll
        for (int mi = 0; mi < 2; mi++) {
            int rb = wm * 32 + mi * 16 + grp;
            a[mi][0] = __float_as_uint(As[rb * LDS_STRIDE + k0 + tig]);
            a[mi][1] = __float_as_uint(As[(rb + 8) * LDS_STRIDE + k0 + tig]);
            a[mi][2] = __float_as_uint(As[rb * LDS_STRIDE + k0 + tig + 4]);
            a[mi][3] = __float_as_uint(As[(rb + 8) * LDS_STRIDE + k0 + tig + 4]);
        }
        uint32_t b[8][2];
#pragma unroll
        for (int ni = 0; ni < 8; ni++) {
            int cb = wn * 64 + ni * 8 + grp;
            b[ni][0] = __float_as_uint(Bs[cb * LDS_STRIDE + k0 + tig]);
            b[ni][1] = __float_as_uint(Bs[cb * LDS_STRIDE + k0 + tig + 4]);
        }
#pragma unroll
        for (int mi = 0; mi < 2; mi++)
#pragma unroll
            for (int ni = 0; ni < 8; ni++) {
                asm volatile(
                    "mma.sync.aligned.m16n8k8.row.col.f32.tf32.tf32.f32 "
                    "{%0,%1,%2,%3}, {%4,%5,%6,%7}, {%8,%9}, {%0,%1,%2,%3};"
                    : "+f"(acc[mi][ni][0]), "+f"(acc[mi][ni][1]),
                      "+f"(acc[mi][ni][2]), "+f"(acc[mi][ni][3])
                    : "r"(a[mi][0]), "r"(a[mi][1]), "r"(a[mi][2]), "r"(a[mi][3]),
                      "r"(b[ni][0]), "r"(b[ni][1]));
            }
    }

    // ---- epilogue: bias/relu/store + fused attention dots ----
#pragma unroll
    for (int mi = 0; mi < 2; mi++) {
        const int r0 = wm * 32 + mi * 16 + grp;
        const int r1 = r0 + 8;
        const int gm0 = m0 + r0, gm1 = m0 + r1;
        float aS0 = 0.f, aD0 = 0.f, aS1 = 0.f, aD1 = 0.f;
#pragma unroll
        for (int ni = 0; ni < 8; ni++) {
            const int col = wn * 64 + ni * 8 + tig * 2;
            const int cg = colg0 + col;
            float v0 = acc[mi][ni][0], v1 = acc[mi][ni][1];
            float v2 = acc[mi][ni][2], v3 = acc[mi][ni][3];
            if (bias) {
                float b0 = bias[cg], b1 = bias[cg + 1];
                v0 += b0; v1 += b1; v2 += b0; v3 += b1;
            }
            if (relu) {
                v0 = fmaxf(v0, 0.f); v1 = fmaxf(v1, 0.f);
                v2 = fmaxf(v2, 0.f); v3 = fmaxf(v3, 0.f);
            }
            if (attS) {
                float s0 = attS[cg], s1 = attS[cg + 1];
                float d0 = attD[cg], d1 = attD[cg + 1];
                aS0 += v0 * s0 + v1 * s1;
                aD0 += v0 * d0 + v1 * d1;
                aS1 += v2 * s0 + v3 * s1;
                aD1 += v2 * d0 + v3 * d1;
            }
            if (gm0 < M) *(float2*)(C + (size_t)gm0 * c_stride + cg) = make_float2(v0, v1);
            if (gm1 < M) *(float2*)(C + (size_t)gm1 * c_stride + cg) = make_float2(v2, v3);
        }
        if (attS) {
            // reduce over the 4 lanes (tig) sharing a row before smem atomics
#pragma unroll
            for (int off = 1; off < 4; off <<= 1) {
                aS0 += __shfl_xor_sync(0xffffffffu, aS0, off);
                aD0 += __shfl_xor_sync(0xffffffffu, aD0, off);
                aS1 += __shfl_xor_sync(0xffffffffu, aS1, off);
                aD1 += __shfl_xor_sync(0xffffffffu, aD1, off);
            }
            if (tig == 0) {
                atomicAdd(&asbuf[r0], aS0);
                atomicAdd(&adbuf[r0], aD0);
                atomicAdd(&asbuf[r1], aS1);
                atomicAdd(&adbuf[r1], aD1);
            }
        }
    }
    if (attS) {
        __syncthreads();
        if (tid < BMROWS && m0 + tid < M) {
            asOut[(m0 + tid) * HH + nc] = asbuf[tid];
            adOut[(m0 + tid) * HH + nc] = adbuf[tid];
        }
    }
}

// ---------------- SIMT SGEMM (FC2 only: K=1024) ------------------------------
template <int BM, int BN, int BK, int TM, int TN>
__global__ void __launch_bounds__((BM / TM) * (BN / TN))
sgemm_kernel(const float* __restrict__ A, const float* __restrict__ B,
             const float* __restrict__ bias, float* __restrict__ C,
             int M, int N, int K, int relu)
{
    constexpr int TX = BN / TN;
    constexpr int TY = BM / TM;
    constexpr int THREADS = TX * TY;
    __shared__ float As[BK][BM];
    __shared__ float Bs[BK][BN];

    const int tid = threadIdx.x;
    const int tx = tid % TX;
    const int ty = tid / TX;
    const int row0 = blockIdx.y * BM;
    const int col0 = blockIdx.x * BN;

    float acc[TM][TN];
#pragma unroll
    for (int i = 0; i < TM; i++)
#pragma unroll
        for (int j = 0; j < TN; j++) acc[i][j] = 0.f;

    for (int k0 = 0; k0 < K; k0 += BK) {
        for (int i = tid; i < BM * BK; i += THREADS) {
            int m = i / BK, k = i % BK;
            int gm = row0 + m, gk = k0 + k;
            As[k][m] = (gm < M && gk < K) ? A[(size_t)gm * K + gk] : 0.f;
        }
        for (int i = tid; i < BK * BN; i += THREADS) {
            int k = i / BN, nn = i % BN;
            int gn = col0 + nn, gk = k0 + k;
            Bs[k][nn] = (gn < N && gk < K) ? B[(size_t)gk * N + gn] : 0.f;
        }
        __syncthreads();
#pragma unroll
        for (int k = 0; k < BK; k++) {
            float ra[TM], rb[TN];
#pragma unroll
            for (int i = 0; i < TM; i++) ra[i] = As[k][ty * TM + i];
#pragma unroll
            for (int j = 0; j < TN; j++) rb[j] = Bs[k][tx * TN + j];
#pragma unroll
            for (int i = 0; i < TM; i++)
#pragma unroll
                for (int j = 0; j < TN; j++) acc[i][j] += ra[i] * rb[j];
        }
        __syncthreads();
    }

#pragma unroll
    for (int i = 0; i < TM; i++) {
        int gm = row0 + ty * TM + i;
        if (gm >= M) continue;
#pragma unroll
        for (int j = 0; j < TN; j++) {
            int gn = col0 + tx * TN + j;
            if (gn >= N) continue;
            float v = acc[i][j];
            if (bias) v += bias[gn];
            if (relu) v = fmaxf(v, 0.f);
            C[(size_t)gm * N + gn] = v;
        }
    }
}

// ---------------- CSR build (edge_index is int32) ---------------------------
__global__ void hist_kernel(const int* __restrict__ ei, int* __restrict__ cnt) {
    int e = blockIdx.x * blockDim.x + threadIdx.x;
    if (e < EE) atomicAdd(&cnt[ei[EE + e]], 1);
}

__global__ void scan_kernel(const int* __restrict__ cnt, int* __restrict__ rowptr) {
    __shared__ int sh[1024];
    const int tid = threadIdx.x;
    int carry = 0;
    if (tid == 0) rowptr[0] = 0;
    for (int base = 0; base < NN; base += 1024) {
        int v = (base + tid < NN) ? cnt[base + tid] : 0;
        sh[tid] = v;
        __syncthreads();
        for (int off = 1; off < 1024; off <<= 1) {
            int t = (tid >= off) ? sh[tid - off] : 0;
            __syncthreads();
            sh[tid] += t;
            __syncthreads();
        }
        if (base + tid < NN) rowptr[base + tid + 1] = carry + sh[tid];
        int tot = sh[1023];
        __syncthreads();
        carry += tot;
    }
}

__global__ void scatter_kernel(const int* __restrict__ ei,
                               const int* __restrict__ rowptr,
                               int* __restrict__ cur, int* __restrict__ colA) {
    int e = blockIdx.x * blockDim.x + threadIdx.x;
    if (e < EE) {
        int d = ei[EE + e];
        int pos = atomicAdd(&cur[d], 1);
        colA[rowptr[d] + pos] = ei[e];
    }
}

// ---------------- GAT aggregation: segment softmax + weighted sum ----------
#define AGG_CHUNK 256
__global__ void gat_aggregate_kernel(const float* __restrict__ hp,
                                     const float* __restrict__ as_,
                                     const float* __restrict__ ad_,
                                     const int* __restrict__ rowptr,
                                     const int* __restrict__ col,
                                     const float* __restrict__ bias,
                                     float* __restrict__ hout) {
    const int n = blockIdx.x;
    const int tid = threadIdx.x;
    const int start = rowptr[n];
    const int deg = rowptr[n + 1] - start;
    const int total = deg + 1;

    float adh[HH];
#pragma unroll
    for (int h = 0; h < HH; h++) adh[h] = ad_[n * HH + h];

    __shared__ float4 red[128];
    __shared__ float  wbuf[AGG_CHUNK * HH];
    __shared__ int    sbuf[AGG_CHUNK];

    float lm[HH] = {-1e30f, -1e30f, -1e30f, -1e30f};
    for (int i = tid; i < total; i += 128) {
        int s = (i < deg) ? col[start + i] : n;
#pragma unroll
        for (int h = 0; h < HH; h++) {
            float e = as_[s * HH + h] + adh[h];
            e = e > 0.f ? e : 0.2f * e;
            lm[h] = fmaxf(lm[h], e);
        }
    }
    red[tid] = make_float4(lm[0], lm[1], lm[2], lm[3]);
    __syncthreads();
    for (int s = 64; s > 0; s >>= 1) {
        if (tid < s) {
            float4 a = red[tid], b = red[tid + s];
            red[tid] = make_float4(fmaxf(a.x, b.x), fmaxf(a.y, b.y),
                                   fmaxf(a.z, b.z), fmaxf(a.w, b.w));
        }
        __syncthreads();
    }
    float4 m4 = red[0];
    float mh[HH] = {m4.x, m4.y, m4.z, m4.w};
    __syncthreads();

    float num[HH] = {0.f, 0.f, 0.f, 0.f};
    float dl[HH] = {0.f, 0.f, 0.f, 0.f};
    for (int base = 0; base < total; base += AGG_CHUNK) {
        int cnt = min(AGG_CHUNK, total - base);
        for (int i = tid; i < cnt; i += 128) {
            int s = (base + i < deg) ? col[start + base + i] : n;
            sbuf[i] = s;
#pragma unroll
            for (int h = 0; h < HH; h++) {
                float e = as_[s * HH + h] + adh[h];
                e = e > 0.f ? e : 0.2f * e;
                float w = __expf(e - mh[h]);
                wbuf[i * HH + h] = w;
                dl[h] += w;
            }
        }
        __syncthreads();
#pragma unroll 4
        for (int i = 0; i < cnt; i++) {
            int s = sbuf[i];
            const float* hr = hp + (size_t)s * (HH * DD) + tid;
#pragma unroll
            for (int h = 0; h < HH; h++) num[h] += wbuf[i * HH + h] * hr[h * DD];
        }
        __syncthreads();
    }

    red[tid] = make_float4(dl[0], dl[1], dl[2], dl[3]);
    __syncthreads();
    for (int s = 64; s > 0; s >>= 1) {
        if (tid < s) {
            float4 a = red[tid], b = red[tid + s];
            red[tid] = make_float4(a.x + b.x, a.y + b.y, a.z + b.z, a.w + b.w);
        }
        __syncthreads();
    }
    float4 dn = red[0];
    float o = 0.25f * (num[0] / (dn.x + 1e-16f) + num[1] / (dn.y + 1e-16f) +
                       num[2] / (dn.z + 1e-16f) + num[3] / (dn.w + 1e-16f));
    hout[(size_t)n * DD + tid] = o + bias[tid];
}

// ---------------- pooling ---------------------------------------------------
__global__ void pool_accum_kernel(const float* __restrict__ hin,
                                  const int* __restrict__ batch,
                                  float* __restrict__ pooled, int* __restrict__ gcnt) {
    int n = blockIdx.x;
    int c = threadIdx.x;
    int g = batch[n];
    if (c == 0) atomicAdd(&gcnt[g], 1);
    atomicAdd(&pooled[g * DD + c], hin[(size_t)n * DD + c]);
}
__global__ void pool_finalize_kernel(float* __restrict__ pooled,
                                     const int* __restrict__ gcnt) {
    int g = blockIdx.x;
    int c = threadIdx.x;
    float cf = fmaxf((float)gcnt[g], 1.f);
    pooled[g * DD + c] /= cf;
}

// ---------------- launch ----------------------------------------------------
extern "C" void kernel_launch(void* const* d_in, const int* in_sizes, int n_in,
                              void* d_out, int out_size) {
    const float* x       = (const float*)d_in[0];
    const int*   ei      = (const int*)d_in[1];
    const int*   batch   = (const int*)d_in[2];
    const float* W1      = (const float*)d_in[3];
    const float* b1      = (const float*)d_in[4];
    const float* W2      = (const float*)d_in[5];
    const float* b2      = (const float*)d_in[6];
    const float* lin_w   = (const float*)d_in[7];
    const float* att_src = (const float*)d_in[8];
    const float* att_dst = (const float*)d_in[9];
    const float* conv_b  = (const float*)d_in[10];
    const float* gW1     = (const float*)d_in[11];
    const float* gb1     = (const float*)d_in[12];
    const float* gW2     = (const float*)d_in[13];
    const float* gb2     = (const float*)d_in[14];
    float*       out     = (float*)d_out;

    float *h, *hp, *hn, *as_, *ad_, *pooled, *hidden, *wT;
    int *rowptr, *cnt, *colA, *gcnt;
    cudaGetSymbolAddress((void**)&h, g_h);
    cudaGetSymbolAddress((void**)&hp, g_hp);
    cudaGetSymbolAddress((void**)&hn, g_hn);
    cudaGetSymbolAddress((void**)&as_, g_as);
    cudaGetSymbolAddress((void**)&ad_, g_ad);
    cudaGetSymbolAddress((void**)&rowptr, g_rowptr);
    cudaGetSymbolAddress((void**)&cnt, g_cnt);
    cudaGetSymbolAddress((void**)&colA, g_col);
    cudaGetSymbolAddress((void**)&pooled, g_pooled);
    cudaGetSymbolAddress((void**)&gcnt, g_gcnt);
    cudaGetSymbolAddress((void**)&hidden, g_hidden);
    cudaGetSymbolAddress((void**)&wT, g_wT);

    float* w1T  = wT;                                    // [128][128]
    float* w2T  = wT + 128 * 128;                        // [128][128]
    float* linT = wT + 2 * 128 * 128;                    // [3][512][128]
    float* gW1T = wT + 2 * 128 * 128 + 3 * 512 * 128;    // [1024][128]

    cudaFuncSetAttribute(tf32_gemm_fused,
                         cudaFuncAttributeMaxDynamicSharedMemorySize, SM_BYTES);

    auto cdiv = [](int a, int b) { return (a + b - 1) / b; };
    const int MT = cdiv(NN, BMROWS);  // 196 m-tiles of 256 rows

    // 0) transpose/pad weights
    transpose_pad_kernel<<<dim3(4, 4), dim3(32, 8)>>>(W1, NODE_DIM, DD, w1T);
    transpose_pad_kernel<<<dim3(4, 4), dim3(32, 8)>>>(W2, DD, DD, w2T);
    for (int l = 0; l < LL; l++)
        transpose_pad_kernel<<<dim3(16, 4), dim3(32, 8)>>>(
            lin_w + (size_t)l * DD * HH * DD, DD, HH * DD, linT + (size_t)l * 512 * 128);
    transpose_pad_kernel<<<dim3(32, 4), dim3(32, 8)>>>(gW1, DD, HID, gW1T);

    // 1) node MLP via tensor cores (tmp = hn)
    tf32_gemm_fused<<<dim3(1, MT), GTHREADS, SM_BYTES>>>(
        x, NN, NODE_DIM, w1T, b1, hn, DD, 1, nullptr, nullptr, nullptr, nullptr);
    tf32_gemm_fused<<<dim3(1, MT), GTHREADS, SM_BYTES>>>(
        hn, NN, DD, w2T, b2, h, DD, 0, nullptr, nullptr, nullptr, nullptr);

    // 2) CSR by destination
    zero_int_kernel<<<cdiv(NN, 256), 256>>>(cnt, NN);
    hist_kernel<<<cdiv(EE, 256), 256>>>(ei, cnt);
    scan_kernel<<<1, 1024>>>(cnt, rowptr);
    zero_int_kernel<<<cdiv(NN, 256), 256>>>(cnt, NN);
    scatter_kernel<<<cdiv(EE, 256), 256>>>(ei, rowptr, cnt, colA);

    // 3) GAT layers: fused projection + attention dots, then aggregate
    float* hin = h;
    float* hout = hn;
    for (int l = 0; l < LL; l++) {
        tf32_gemm_fused<<<dim3(HH, MT), GTHREADS, SM_BYTES>>>(
            hin, NN, DD, linT + (size_t)l * 512 * 128, nullptr, hp, HH * DD, 0,
            att_src + l * HH * DD, att_dst + l * HH * DD, as_, ad_);
        gat_aggregate_kernel<<<NN, 128>>>(hp, as_, ad_, rowptr, colA,
                                          conv_b + l * DD, hout);
        float* t = hin; hin = hout; hout = t;
    }

    // 4) global mean pool
    zero_float_kernel<<<cdiv(GG * DD, 256), 256>>>(pooled, GG * DD);
    zero_int_kernel<<<cdiv(GG, 256), 256>>>(gcnt, GG);
    pool_accum_kernel<<<NN, DD>>>(hin, batch, pooled, gcnt);
    pool_finalize_kernel<<<GG, DD>>>(pooled, gcnt);

    // 5) FC head: FC1 on tensor cores, FC2 (K=1024) SIMT
    tf32_gemm_fused<<<dim3(8, cdiv(GG, BMROWS)), GTHREADS, SM_BYTES>>>(
        pooled, GG, DD, gW1T, gb1, hidden, HID, 1, nullptr, nullptr, nullptr, nullptr);
    sgemm_kernel<64, 64, 8, 4, 4><<<dim3(cdiv(DD, 64), cdiv(GG, 64)), 256>>>(
        hidden, gW2, gb2, out, GG, DD, HID, 0);
}